// round 3
// baseline (speedup 1.0000x reference)
#include <cuda_runtime.h>

// BiologicalNormalization: 3 chained per-row LayerNorms (D=512), gathered
// affine params; trailing sigmoid-gated blend is the identity -> skipped.
//
// R3: params register-resident (no per-row smem reads). A row is processed
// by a warp-PAIR (64 threads x 8 floats). Cross-warp stats via a tiny smem
// slot + named barrier. Next-row prefetch keeps DRAM MLP high.

#define B_DIM 2048
#define S_DIM 128
#define D_DIM 512
#define THREADS 256
#define PAIRS 4                      // warp-pairs per block
#define SPLIT 2                      // blocks per sample
#define ROWS_PER_PAIR (S_DIM / SPLIT / PAIRS)   // 16

__global__ __launch_bounds__(THREADS, 3)
void bionorm_kernel(const float* __restrict__ x,
                    const int* __restrict__ pathway_ids,
                    const int* __restrict__ compartment_ids,
                    const int* __restrict__ cell_type_ids,
                    const float* __restrict__ pg, const float* __restrict__ pb,
                    const float* __restrict__ cg, const float* __restrict__ cb,
                    const float* __restrict__ tg, const float* __restrict__ tb,
                    float* __restrict__ out)
{
    // [pair][pass][warp-in-pair] -> (sum, sumsq)
    __shared__ float2 xch[PAIRS][3][2];

    const int blk = blockIdx.x;
    const int b = blk / SPLIT;
    const int half = blk % SPLIT;

    const int tid  = threadIdx.x;
    const int lane = tid & 31;
    const int warp = tid >> 5;
    const int pair = warp >> 1;       // 0..3
    const int wip  = warp & 1;        // warp-in-pair
    const int q    = tid & 63;        // float4 slice base within row (0..63)

    const int p_id = pathway_ids[b];
    const int c_id = compartment_ids[b];
    const int t_id = cell_type_ids[b];

    // Register-resident params: 6 vectors x 8 floats per thread = 48 regs.
    const float* gp[3] = { pg + (size_t)p_id * D_DIM,
                           cg + (size_t)c_id * D_DIM,
                           tg + (size_t)t_id * D_DIM };
    const float* bp[3] = { pb + (size_t)p_id * D_DIM,
                           cb + (size_t)c_id * D_DIM,
                           tb + (size_t)t_id * D_DIM };
    float4 g[3][2], be[3][2];
    #pragma unroll
    for (int p = 0; p < 3; p++) {
        #pragma unroll
        for (int i = 0; i < 2; i++) {
            g[p][i]  = reinterpret_cast<const float4*>(gp[p])[q + 64 * i];
            be[p][i] = reinterpret_cast<const float4*>(bp[p])[q + 64 * i];
        }
    }

    const float inv_d = 1.0f / (float)D_DIM;
    const float eps = 1e-5f;

    // This pair's contiguous row range.
    const int s0 = half * (S_DIM / SPLIT) + pair * ROWS_PER_PAIR;
    const size_t base = ((size_t)b * S_DIM + s0) * D_DIM;

    volatile float2 (*xc)[2] = xch[pair];
    const int barid = pair + 1;       // named barriers 1..4, 64 threads each

    // Preload first row.
    float4 v0, v1;
    {
        const float4* xr = reinterpret_cast<const float4*>(x + base);
        v0 = xr[q];
        v1 = xr[q + 64];
    }

    for (int k = 0; k < ROWS_PER_PAIR; k++) {
        // Prefetch next row while this one computes.
        float4 n0, n1;
        if (k + 1 < ROWS_PER_PAIR) {
            const float4* xr = reinterpret_cast<const float4*>(
                x + base + (size_t)(k + 1) * D_DIM);
            n0 = xr[q];
            n1 = xr[q + 64];
        } else {
            n0 = v0; n1 = v1;
        }

        #pragma unroll
        for (int p = 0; p < 3; p++) {
            float sum = v0.x + v0.y + v0.z + v0.w
                      + v1.x + v1.y + v1.z + v1.w;
            float sq = 0.f;
            sq = fmaf(v0.x, v0.x, sq); sq = fmaf(v0.y, v0.y, sq);
            sq = fmaf(v0.z, v0.z, sq); sq = fmaf(v0.w, v0.w, sq);
            sq = fmaf(v1.x, v1.x, sq); sq = fmaf(v1.y, v1.y, sq);
            sq = fmaf(v1.z, v1.z, sq); sq = fmaf(v1.w, v1.w, sq);

            #pragma unroll
            for (int o = 16; o > 0; o >>= 1) {
                sum += __shfl_xor_sync(0xffffffffu, sum, o);
                sq  += __shfl_xor_sync(0xffffffffu, sq,  o);
            }
            if (lane == 0) {
                xc[p][wip].x = sum;
                xc[p][wip].y = sq;
            }
            asm volatile("bar.sync %0, %1;" :: "r"(barid), "r"(64) : "memory");
            sum = xc[p][0].x + xc[p][1].x;
            sq  = xc[p][0].y + xc[p][1].y;

            const float mean = sum * inv_d;
            const float var  = fmaf(-mean, mean, sq * inv_d);
            const float rstd = rsqrtf(var + eps);

            v0.x = fmaf((v0.x - mean) * rstd, g[p][0].x, be[p][0].x);
            v0.y = fmaf((v0.y - mean) * rstd, g[p][0].y, be[p][0].y);
            v0.z = fmaf((v0.z - mean) * rstd, g[p][0].z, be[p][0].z);
            v0.w = fmaf((v0.w - mean) * rstd, g[p][0].w, be[p][0].w);
            v1.x = fmaf((v1.x - mean) * rstd, g[p][1].x, be[p][1].x);
            v1.y = fmaf((v1.y - mean) * rstd, g[p][1].y, be[p][1].y);
            v1.z = fmaf((v1.z - mean) * rstd, g[p][1].z, be[p][1].z);
            v1.w = fmaf((v1.w - mean) * rstd, g[p][1].w, be[p][1].w);
        }

        float4* orow = reinterpret_cast<float4*>(out + base + (size_t)k * D_DIM);
        orow[q]      = v0;
        orow[q + 64] = v1;

        v0 = n0;
        v1 = n1;
    }
}

extern "C" void kernel_launch(void* const* d_in, const int* in_sizes, int n_in,
                              void* d_out, int out_size)
{
    const float* x  = (const float*)d_in[0];
    const int* pid  = (const int*)d_in[1];
    const int* cid  = (const int*)d_in[2];
    const int* tid  = (const int*)d_in[3];
    const float* pg = (const float*)d_in[4];
    const float* pb = (const float*)d_in[5];
    const float* cg = (const float*)d_in[6];
    const float* cb = (const float*)d_in[7];
    const float* tg = (const float*)d_in[8];
    const float* tb = (const float*)d_in[9];
    // d_in[10] = W, d_in[11] = b : unused (gated blend is the identity)
    float* out = (float*)d_out;

    dim3 grid(B_DIM * SPLIT);
    dim3 block(THREADS);
    bionorm_kernel<<<grid, block>>>(x, pid, cid, tid,
                                    pg, pb, cg, cb, tg, tb, out);
}

// round 4
// speedup vs baseline: 1.3757x; 1.3757x over previous
#include <cuda_runtime.h>

// BiologicalNormalization: 3 chained per-row LayerNorms (D=512), gathered
// per-sample affine params; trailing sigmoid-gated blend is the identity.
//
// R4: warp-per-row x 4 rows simultaneously. One param load (L1-cached __ldg)
// serves 4 rows -> param L1 traffic /4 vs R2. No smem, no block barriers;
// all reductions warp-internal. 16 front-batched LDG.128 per warp for MLP.

#define B_DIM 2048
#define S_DIM 128
#define D_DIM 512
#define THREADS 256
#define WARPS 8
#define ROWS 4            // rows per warp (8 warps * 4 = 32 rows per block)
#define SPLIT 4           // blocks per sample

__global__ __launch_bounds__(THREADS, 2)
void bionorm_kernel(const float* __restrict__ x,
                    const int* __restrict__ pathway_ids,
                    const int* __restrict__ compartment_ids,
                    const int* __restrict__ cell_type_ids,
                    const float* __restrict__ pg, const float* __restrict__ pb,
                    const float* __restrict__ cg, const float* __restrict__ cb,
                    const float* __restrict__ tg, const float* __restrict__ tb,
                    float* __restrict__ out)
{
    const int blk = blockIdx.x;
    const int b = blk >> 2;           // sample
    const int chunk = blk & 3;        // 32-row chunk within sample
    const int warp = threadIdx.x >> 5;
    const int lane = threadIdx.x & 31;

    // Gather ids early (address deps for param loads).
    const int p_id = __ldg(pathway_ids + b);
    const int c_id = __ldg(compartment_ids + b);
    const int t_id = __ldg(cell_type_ids + b);

    const int s0 = chunk * 32 + warp * ROWS;
    const size_t base = ((size_t)b * S_DIM + s0) * D_DIM;
    const float4* __restrict__ xr = reinterpret_cast<const float4*>(x + base);

    // Front-batched load of 4 full rows: 16 independent LDG.128.
    float4 v[ROWS][4];
    #pragma unroll
    for (int r = 0; r < ROWS; r++)
        #pragma unroll
        for (int i = 0; i < 4; i++)
            v[r][i] = xr[r * (D_DIM / 4) + lane + 32 * i];

    const float4* __restrict__ gv[3] = {
        reinterpret_cast<const float4*>(pg + (size_t)p_id * D_DIM),
        reinterpret_cast<const float4*>(cg + (size_t)c_id * D_DIM),
        reinterpret_cast<const float4*>(tg + (size_t)t_id * D_DIM)
    };
    const float4* __restrict__ bv[3] = {
        reinterpret_cast<const float4*>(pb + (size_t)p_id * D_DIM),
        reinterpret_cast<const float4*>(cb + (size_t)c_id * D_DIM),
        reinterpret_cast<const float4*>(tb + (size_t)t_id * D_DIM)
    };

    const float inv_d = 1.0f / (float)D_DIM;
    const float eps = 1e-5f;

    #pragma unroll
    for (int p = 0; p < 3; p++) {
        // Per-row sum and sum-of-squares (local), then packed shuffle-reduce.
        float sum[ROWS], sq[ROWS];
        #pragma unroll
        for (int r = 0; r < ROWS; r++) {
            float s = 0.f, q = 0.f;
            #pragma unroll
            for (int i = 0; i < 4; i++) {
                s += v[r][i].x + v[r][i].y + v[r][i].z + v[r][i].w;
                q = fmaf(v[r][i].x, v[r][i].x, q);
                q = fmaf(v[r][i].y, v[r][i].y, q);
                q = fmaf(v[r][i].z, v[r][i].z, q);
                q = fmaf(v[r][i].w, v[r][i].w, q);
            }
            sum[r] = s; sq[r] = q;
        }
        #pragma unroll
        for (int o = 16; o > 0; o >>= 1) {
            #pragma unroll
            for (int r = 0; r < ROWS; r++) {
                sum[r] += __shfl_xor_sync(0xffffffffu, sum[r], o);
                sq[r]  += __shfl_xor_sync(0xffffffffu, sq[r],  o);
            }
        }

        float mean[ROWS], rstd[ROWS];
        #pragma unroll
        for (int r = 0; r < ROWS; r++) {
            mean[r] = sum[r] * inv_d;
            const float var = fmaf(-mean[r], mean[r], sq[r] * inv_d);
            rstd[r] = rsqrtf(var + eps);
        }

        // One param load serves all 4 rows.
        #pragma unroll
        for (int i = 0; i < 4; i++) {
            const float4 gg = __ldg(gv[p] + lane + 32 * i);
            const float4 bb = __ldg(bv[p] + lane + 32 * i);
            #pragma unroll
            for (int r = 0; r < ROWS; r++) {
                v[r][i].x = fmaf((v[r][i].x - mean[r]) * rstd[r], gg.x, bb.x);
                v[r][i].y = fmaf((v[r][i].y - mean[r]) * rstd[r], gg.y, bb.y);
                v[r][i].z = fmaf((v[r][i].z - mean[r]) * rstd[r], gg.z, bb.z);
                v[r][i].w = fmaf((v[r][i].w - mean[r]) * rstd[r], gg.w, bb.w);
            }
        }
    }

    float4* __restrict__ orow = reinterpret_cast<float4*>(out + base);
    #pragma unroll
    for (int r = 0; r < ROWS; r++)
        #pragma unroll
        for (int i = 0; i < 4; i++)
            orow[r * (D_DIM / 4) + lane + 32 * i] = v[r][i];
}

extern "C" void kernel_launch(void* const* d_in, const int* in_sizes, int n_in,
                              void* d_out, int out_size)
{
    const float* x  = (const float*)d_in[0];
    const int* pid  = (const int*)d_in[1];
    const int* cid  = (const int*)d_in[2];
    const int* tid  = (const int*)d_in[3];
    const float* pg = (const float*)d_in[4];
    const float* pb = (const float*)d_in[5];
    const float* cg = (const float*)d_in[6];
    const float* cb = (const float*)d_in[7];
    const float* tg = (const float*)d_in[8];
    const float* tb = (const float*)d_in[9];
    // d_in[10] = W, d_in[11] = b : unused (gated blend is the identity)
    float* out = (float*)d_out;

    dim3 grid(B_DIM * SPLIT);
    dim3 block(THREADS);
    bionorm_kernel<<<grid, block>>>(x, pid, cid, tid,
                                    pg, pb, cg, cb, tg, tb, out);
}